// round 1
// baseline (speedup 1.0000x reference)
#include <cuda_runtime.h>
#include <cstdint>

// Problem constants
#define ORIG_IN   4096
#define ORIG_OUT  4096
#define ACTIVE    2048
#define RANK      16
#define SCALING   2.0f
#define M_TOK     8192          // 2 * 4096 tokens

// Scratch (device globals: allocation-free per harness rules)
__device__ float g_Wp[ACTIVE * ACTIVE];      // folded weight  [o][a], tf32-rounded
__device__ float g_xsel[(size_t)M_TOK * ACTIVE]; // gathered x [n][a], tf32-rounded

// ---------------------------------------------------------------------------
// tf32 round helper
// ---------------------------------------------------------------------------
__device__ __forceinline__ float to_tf32(float v) {
    uint32_t t;
    asm("cvt.rna.tf32.f32 %0, %1;" : "=r"(t) : "f"(v));
    return __uint_as_float(t);
}

// ---------------------------------------------------------------------------
// Kernel 1: fold LoRA into base weight.  Wp[o][a] = W[o][a] + 2 * sum_r B[o][r]*A[r][a]
// grid = (ACTIVE/256, ACTIVE), block = 256
// ---------------------------------------------------------------------------
__global__ void fold_kernel(const float* __restrict__ W,
                            const float* __restrict__ lA,
                            const float* __restrict__ lB) {
    int a = blockIdx.x * 256 + threadIdx.x;
    int o = blockIdx.y;
    float acc = W[(size_t)o * ACTIVE + a];
#pragma unroll
    for (int r = 0; r < RANK; r++)
        acc += SCALING * lB[o * RANK + r] * lA[r * ACTIVE + a];
    g_Wp[(size_t)o * ACTIVE + a] = to_tf32(acc);
}

// ---------------------------------------------------------------------------
// Kernel 2: gather selected input columns.  xsel[n][a] = x[n][in_idx[a]]
// grid = (ACTIVE/256, M_TOK), block = 256
// ---------------------------------------------------------------------------
__global__ void gather_kernel(const float* __restrict__ x,
                              const int* __restrict__ in_idx) {
    int a = blockIdx.x * 256 + threadIdx.x;
    int n = blockIdx.y;
    float v = x[(size_t)n * ORIG_IN + in_idx[a]];
    g_xsel[(size_t)n * ACTIVE + a] = to_tf32(v);
}

// ---------------------------------------------------------------------------
// Kernel 3: zero the full output (harness poisons it with 0xAA)
// ---------------------------------------------------------------------------
__global__ void zero_kernel(float4* __restrict__ out, int n4) {
    int i = blockIdx.x * blockDim.x + threadIdx.x;
    if (i < n4) out[i] = make_float4(0.f, 0.f, 0.f, 0.f);
}

// ---------------------------------------------------------------------------
// Kernel 4: TF32 mma.sync GEMM  C[n][o] = sum_a xsel[n][a] * Wp[o][a]
// BM=128, BN=128, BK=16, 256 threads (8 warps, 4x2), warp tile 32x64.
// Epilogue: out[n*4096 + out_idx[o]] = C + bias[o]
// ---------------------------------------------------------------------------
#define BM 128
#define BN 128
#define BK 16
#define SPAD 17   // smem row stride (pad to dodge conflicts)

__device__ __forceinline__ void mma_tf32(float c[4], const uint32_t a[4], const uint32_t b[2]) {
    asm volatile(
        "mma.sync.aligned.m16n8k8.row.col.f32.tf32.tf32.f32 "
        "{%0,%1,%2,%3}, {%4,%5,%6,%7}, {%8,%9}, {%0,%1,%2,%3};\n"
        : "+f"(c[0]), "+f"(c[1]), "+f"(c[2]), "+f"(c[3])
        : "r"(a[0]), "r"(a[1]), "r"(a[2]), "r"(a[3]),
          "r"(b[0]), "r"(b[1]));
}

__global__ __launch_bounds__(256)
void gemm_kernel(const float* __restrict__ bias,
                 const int* __restrict__ out_idx,
                 float* __restrict__ out) {
    __shared__ float As[BM][SPAD];   // [m][k]
    __shared__ float Bs[BN][SPAD];   // [n][k]

    const int bm = blockIdx.y;             // 64 tiles of M
    const int bn = blockIdx.x;             // 16 tiles of N
    const int tid = threadIdx.x;
    const int warp = tid >> 5;
    const int lane = tid & 31;
    const int wm = warp >> 1;              // 0..3  -> m offset wm*32
    const int wn = warp & 1;               // 0..1  -> n offset wn*64
    const int group = lane >> 2;           // 0..7
    const int tig = lane & 3;              // 0..3

    float acc[2][8][4];
#pragma unroll
    for (int i = 0; i < 2; i++)
#pragma unroll
        for (int j = 0; j < 8; j++)
#pragma unroll
            for (int k = 0; k < 4; k++) acc[i][j][k] = 0.f;

    const float* Ag = g_xsel + (size_t)(bm * BM) * ACTIVE;
    const float* Bg = g_Wp   + (size_t)(bn * BN) * ACTIVE;

    for (int kt = 0; kt < ACTIVE; kt += BK) {
        __syncthreads();
        // Load A and B tiles: 128 rows x 16 cols each, float4 per quad.
#pragma unroll
        for (int i = 0; i < 2; i++) {
            int id   = tid + i * 256;      // 0..511
            int row  = id >> 2;            // 0..127
            int quad = id & 3;             // 0..3
            float4 va = *(const float4*)(Ag + (size_t)row * ACTIVE + kt + quad * 4);
            As[row][quad * 4 + 0] = va.x;
            As[row][quad * 4 + 1] = va.y;
            As[row][quad * 4 + 2] = va.z;
            As[row][quad * 4 + 3] = va.w;
            float4 vb = *(const float4*)(Bg + (size_t)row * ACTIVE + kt + quad * 4);
            Bs[row][quad * 4 + 0] = vb.x;
            Bs[row][quad * 4 + 1] = vb.y;
            Bs[row][quad * 4 + 2] = vb.z;
            Bs[row][quad * 4 + 3] = vb.w;
        }
        __syncthreads();

#pragma unroll
        for (int ks = 0; ks < 2; ks++) {
            const int k0 = ks * 8;
            uint32_t a[2][4], b[8][2];
#pragma unroll
            for (int mt = 0; mt < 2; mt++) {
                int m = wm * 32 + mt * 16;
                a[mt][0] = __float_as_uint(As[m + group    ][k0 + tig    ]);
                a[mt][1] = __float_as_uint(As[m + group + 8][k0 + tig    ]);
                a[mt][2] = __float_as_uint(As[m + group    ][k0 + tig + 4]);
                a[mt][3] = __float_as_uint(As[m + group + 8][k0 + tig + 4]);
            }
#pragma unroll
            for (int nt = 0; nt < 8; nt++) {
                int n = wn * 64 + nt * 8;
                b[nt][0] = __float_as_uint(Bs[n + group][k0 + tig    ]);
                b[nt][1] = __float_as_uint(Bs[n + group][k0 + tig + 4]);
            }
#pragma unroll
            for (int mt = 0; mt < 2; mt++)
#pragma unroll
                for (int nt = 0; nt < 8; nt++)
                    mma_tf32(acc[mt][nt], a[mt], b[nt]);
        }
    }

    // Epilogue: add bias, scatter to out columns.
#pragma unroll
    for (int mt = 0; mt < 2; mt++) {
        int mrow = bm * BM + wm * 32 + mt * 16 + group;
#pragma unroll
        for (int nt = 0; nt < 8; nt++) {
            int o0 = bn * BN + wn * 64 + nt * 8 + tig * 2;
            int c0 = out_idx[o0];
            int c1 = out_idx[o0 + 1];
            float b0 = bias[o0];
            float b1 = bias[o0 + 1];
            out[(size_t)mrow * ORIG_OUT + c0]       = acc[mt][nt][0] + b0;
            out[(size_t)mrow * ORIG_OUT + c1]       = acc[mt][nt][1] + b1;
            out[(size_t)(mrow + 8) * ORIG_OUT + c0] = acc[mt][nt][2] + b0;
            out[(size_t)(mrow + 8) * ORIG_OUT + c1] = acc[mt][nt][3] + b1;
        }
    }
}

// ---------------------------------------------------------------------------
// Launch
// ---------------------------------------------------------------------------
extern "C" void kernel_launch(void* const* d_in, const int* in_sizes, int n_in,
                              void* d_out, int out_size) {
    const float* x      = (const float*)d_in[0];
    const float* W      = (const float*)d_in[1];
    const float* bias   = (const float*)d_in[2];
    const float* lA     = (const float*)d_in[3];
    const float* lB     = (const float*)d_in[4];
    const int* in_idx   = (const int*)d_in[5];
    const int* out_idx  = (const int*)d_in[6];
    float* out          = (float*)d_out;

    // 1) fold LoRA into weight
    fold_kernel<<<dim3(ACTIVE / 256, ACTIVE), 256>>>(W, lA, lB);
    // 2) gather selected input columns
    gather_kernel<<<dim3(ACTIVE / 256, M_TOK), 256>>>(x, in_idx);
    // 3) zero full output
    {
        int n4 = out_size / 4;
        zero_kernel<<<(n4 + 255) / 256, 256>>>((float4*)d_out, n4);
    }
    // 4) GEMM + bias + scatter
    gemm_kernel<<<dim3(ACTIVE / BN, M_TOK / BM), 256>>>(bias, out_idx, out);
    (void)n_in; (void)in_sizes;
}

// round 4
// speedup vs baseline: 2.0767x; 2.0767x over previous
#include <cuda_runtime.h>
#include <cstdint>

// ---------------------------------------------------------------------------
// Problem constants
// ---------------------------------------------------------------------------
#define ORIG_IN   4096
#define ORIG_OUT  4096
#define ACTIVE    2048
#define RANK      16
#define SCALING   2.0f
#define M_TOK     8192          // 2 * 4096 tokens

// Scratch (device globals: allocation-free per harness rules)
__device__ float g_Wp[ACTIVE * ACTIVE];           // folded weight [o][a], tf32-rounded
__device__ float g_xsel[(size_t)M_TOK * ACTIVE];  // gathered x   [n][a], tf32-rounded

// ---------------------------------------------------------------------------
// Helpers
// ---------------------------------------------------------------------------
__device__ __forceinline__ uint32_t smem_u32(const void* p) {
    uint32_t a;
    asm("{ .reg .u64 t; cvta.to.shared.u64 t, %1; cvt.u32.u64 %0, t; }" : "=r"(a) : "l"(p));
    return a;
}
__device__ __forceinline__ float to_tf32(float v) {
    uint32_t t;
    asm("cvt.rna.tf32.f32 %0, %1;" : "=r"(t) : "f"(v));
    return __uint_as_float(t);
}
__device__ __forceinline__ void cp_async16(uint32_t dst, const float* src) {
    asm volatile("cp.async.cg.shared.global [%0], [%1], 16;" :: "r"(dst), "l"(src));
}
#define CP_COMMIT() asm volatile("cp.async.commit_group;" ::: "memory")
#define CP_WAIT2()  asm volatile("cp.async.wait_group 2;" ::: "memory")

__device__ __forceinline__ float lds_f32(uint32_t addr) {
    float v;
    asm volatile("ld.shared.f32 %0, [%1];" : "=f"(v) : "r"(addr));
    return v;
}

__device__ __forceinline__ void mma_tf32(float c[4], const float a[4], const float b[2]) {
    asm volatile(
        "mma.sync.aligned.m16n8k8.row.col.f32.tf32.tf32.f32 "
        "{%0,%1,%2,%3}, {%4,%5,%6,%7}, {%8,%9}, {%0,%1,%2,%3};\n"
        : "+f"(c[0]), "+f"(c[1]), "+f"(c[2]), "+f"(c[3])
        : "r"(__float_as_uint(a[0])), "r"(__float_as_uint(a[1])),
          "r"(__float_as_uint(a[2])), "r"(__float_as_uint(a[3])),
          "r"(__float_as_uint(b[0])), "r"(__float_as_uint(b[1])));
}

// ---------------------------------------------------------------------------
// Kernel 1: fold LoRA into base weight. Wp[o][a] = W[o][a] + 2*sum_r B[o][r]*A[r][a]
// ---------------------------------------------------------------------------
__global__ void fold_kernel(const float* __restrict__ W,
                            const float* __restrict__ lA,
                            const float* __restrict__ lB) {
    int a = blockIdx.x * 256 + threadIdx.x;
    int o = blockIdx.y;
    float acc = W[(size_t)o * ACTIVE + a];
#pragma unroll
    for (int r = 0; r < RANK; r++)
        acc += SCALING * lB[o * RANK + r] * lA[r * ACTIVE + a];
    g_Wp[(size_t)o * ACTIVE + a] = to_tf32(acc);
}

// ---------------------------------------------------------------------------
// Kernel 2: gather selected input columns. xsel[n][a] = x[n][in_idx[a]]
// ---------------------------------------------------------------------------
__global__ void gather_kernel(const float* __restrict__ x,
                              const int* __restrict__ in_idx) {
    int a = blockIdx.x * 256 + threadIdx.x;
    int n = blockIdx.y;
    float v = x[(size_t)n * ORIG_IN + in_idx[a]];
    g_xsel[(size_t)n * ACTIVE + a] = to_tf32(v);
}

// ---------------------------------------------------------------------------
// Kernel 3: zero the full output (harness poisons it with 0xAA)
// ---------------------------------------------------------------------------
__global__ void zero_kernel(float4* __restrict__ out, int n4) {
    int i = blockIdx.x * blockDim.x + threadIdx.x;
    if (i < n4) out[i] = make_float4(0.f, 0.f, 0.f, 0.f);
}

// ---------------------------------------------------------------------------
// Kernel 4: pipelined mma.sync TF32 GEMM.  C[n][o] = sum_a xsel[n][a]*Wp[o][a]
//   CTA tile 128x128, BK=32, 4-stage cp.async ring, 256 threads (8 warps 2x4),
//   warp tile 64x32, conflict-free XOR-swizzled smem, dbl-buffered fragments.
//   Epilogue: out[n*4096 + out_idx[o]] = C + bias[o]
// ---------------------------------------------------------------------------
#define BM 128
#define BN 128
#define BKF 32                       // K floats per chunk (128 B rows)
#define NCHUNK (ACTIVE / BKF)        // 64
#define NSTAGE 4
#define A_BYTES (BM * BKF * 4)       // 16384
#define STAGE_BYTES ((BM + BN) * BKF * 4)   // 32768
#define GEMM_SMEM (NSTAGE * STAGE_BYTES)    // 131072

// smem swizzle: element (row, colFloat) -> row*128 + ((colFloat*4) ^ ((row&7)*16))
// 16B chunk c (0..7) of row:            -> row*128 + ((c*16)      ^ ((row&7)*16))

__global__ __launch_bounds__(256, 1)
void gemm_mma_kernel(const float* __restrict__ bias,
                     const int* __restrict__ out_idx,
                     float* __restrict__ out) {
    extern __shared__ char smem[];
    const uint32_t sbase = smem_u32(smem);
    const int tid  = threadIdx.x;
    const int lane = tid & 31;
    const int wid  = tid >> 5;
    const int wm   = wid & 1;            // 0..1 -> m offset wm*64
    const int wn   = wid >> 1;           // 0..3 -> n offset wn*32
    const int g    = lane >> 2;          // 0..7
    const int t    = lane & 3;           // 0..3
    const int bm   = blockIdx.y;         // 0..63
    const int bn   = blockIdx.x;         // 0..15

    // ---- per-thread cp.async assignments (4 A chunks + 4 B chunks) ----
    const float* __restrict__ Ag = g_xsel + (size_t)(bm * BM) * ACTIVE;
    const float* __restrict__ Bg = g_Wp   + (size_t)(bn * BN) * ACTIVE;

    const float* asrc[4]; const float* bsrc[4];
    uint32_t aoff[4], boff[4];
#pragma unroll
    for (int i = 0; i < 4; i++) {
        int idx = tid + i * 256;         // 0..1023
        int row = idx >> 3;              // 0..127
        int c   = idx & 7;               // 16B chunk in row
        uint32_t sw = (uint32_t)(row * 128 + ((c * 16) ^ ((row & 7) * 16)));
        asrc[i] = Ag + (size_t)row * ACTIVE + c * 4;
        aoff[i] = sw;
        bsrc[i] = Bg + (size_t)row * ACTIVE + c * 4;
        boff[i] = A_BYTES + sw;
    }

    // ---- fragment address bases ----
    // xk[ks]: per-lane XOR'd column byte offset for k-step ks (col = ks*8 + t)
    uint32_t xk[4];
#pragma unroll
    for (int ks = 0; ks < 4; ks++)
        xk[ks] = (uint32_t)(((ks * 32 + t * 4)) ^ (g * 16));
    uint32_t aRow[4], bRow[4];
#pragma unroll
    for (int mt = 0; mt < 4; mt++) aRow[mt] = (uint32_t)((wm * 64 + mt * 16 + g) * 128);
#pragma unroll
    for (int nt = 0; nt < 4; nt++) bRow[nt] = (uint32_t)(A_BYTES + (wn * 32 + nt * 8 + g) * 128);

    float acc[4][4][4];
#pragma unroll
    for (int mt = 0; mt < 4; mt++)
#pragma unroll
        for (int nt = 0; nt < 4; nt++)
#pragma unroll
            for (int r = 0; r < 4; r++) acc[mt][nt][r] = 0.f;

    // ---- prologue: stages 0..2 ----
#pragma unroll
    for (int s = 0; s < 3; s++) {
        const int k0 = s * BKF;
#pragma unroll
        for (int i = 0; i < 4; i++) cp_async16(sbase + s * STAGE_BYTES + aoff[i], asrc[i] + k0);
#pragma unroll
        for (int i = 0; i < 4; i++) cp_async16(sbase + s * STAGE_BYTES + boff[i], bsrc[i] + k0);
        CP_COMMIT();
    }

    float fa[2][4][4], fb[2][4][2];

    // ---- main loop ----
#pragma unroll 1
    for (int c = 0; c < NCHUNK; c++) {
        CP_WAIT2();
        __syncthreads();

        // issue loads for chunk c+3 into the stage just freed
        if (c + 3 < NCHUNK) {
            const int s2 = (c + 3) & (NSTAGE - 1);
            const int k0 = (c + 3) * BKF;
            const uint32_t sb2 = sbase + s2 * STAGE_BYTES;
#pragma unroll
            for (int i = 0; i < 4; i++) cp_async16(sb2 + aoff[i], asrc[i] + k0);
#pragma unroll
            for (int i = 0; i < 4; i++) cp_async16(sb2 + boff[i], bsrc[i] + k0);
        }
        CP_COMMIT();

        const uint32_t sb = sbase + (c & (NSTAGE - 1)) * STAGE_BYTES;

        // load fragments for ks=0
#pragma unroll
        for (int mt = 0; mt < 4; mt++) {
            uint32_t a0 = sb + aRow[mt] + xk[0];
            fa[0][mt][0] = lds_f32(a0);
            fa[0][mt][1] = lds_f32(a0 + 1024);
            fa[0][mt][2] = lds_f32(a0 ^ 16);
            fa[0][mt][3] = lds_f32((a0 + 1024) ^ 16);
        }
#pragma unroll
        for (int nt = 0; nt < 4; nt++) {
            uint32_t b0 = sb + bRow[nt] + xk[0];
            fb[0][nt][0] = lds_f32(b0);
            fb[0][nt][1] = lds_f32(b0 ^ 16);
        }

#pragma unroll
        for (int ks = 0; ks < 4; ks++) {
            const int cur = ks & 1;
            if (ks < 3) {
                const int nxt = cur ^ 1;
#pragma unroll
                for (int mt = 0; mt < 4; mt++) {
                    uint32_t a0 = sb + aRow[mt] + xk[ks + 1];
                    fa[nxt][mt][0] = lds_f32(a0);
                    fa[nxt][mt][1] = lds_f32(a0 + 1024);
                    fa[nxt][mt][2] = lds_f32(a0 ^ 16);
                    fa[nxt][mt][3] = lds_f32((a0 + 1024) ^ 16);
                }
#pragma unroll
                for (int nt = 0; nt < 4; nt++) {
                    uint32_t b0 = sb + bRow[nt] + xk[ks + 1];
                    fb[nxt][nt][0] = lds_f32(b0);
                    fb[nxt][nt][1] = lds_f32(b0 ^ 16);
                }
            }
#pragma unroll
            for (int mt = 0; mt < 4; mt++)
#pragma unroll
                for (int nt = 0; nt < 4; nt++)
                    mma_tf32(acc[mt][nt], fa[cur][mt], fb[cur][nt]);
        }
        __syncthreads();
    }

    // ---- epilogue: bias + column scatter ----
#pragma unroll
    for (int mt = 0; mt < 4; mt++) {
        const int mrow = bm * BM + wm * 64 + mt * 16 + g;
        float* orow0 = out + (size_t)mrow * ORIG_OUT;
        float* orow1 = out + (size_t)(mrow + 8) * ORIG_OUT;
#pragma unroll
        for (int nt = 0; nt < 4; nt++) {
            const int o0 = bn * BN + wn * 32 + nt * 8 + t * 2;
            const int c0 = __ldg(out_idx + o0);
            const int c1 = __ldg(out_idx + o0 + 1);
            const float b0 = __ldg(bias + o0);
            const float b1 = __ldg(bias + o0 + 1);
            orow0[c0] = acc[mt][nt][0] + b0;
            orow0[c1] = acc[mt][nt][1] + b1;
            orow1[c0] = acc[mt][nt][2] + b0;
            orow1[c1] = acc[mt][nt][3] + b1;
        }
    }
}

// ---------------------------------------------------------------------------
// Launch
// ---------------------------------------------------------------------------
extern "C" void kernel_launch(void* const* d_in, const int* in_sizes, int n_in,
                              void* d_out, int out_size) {
    const float* x      = (const float*)d_in[0];
    const float* W      = (const float*)d_in[1];
    const float* bias   = (const float*)d_in[2];
    const float* lA     = (const float*)d_in[3];
    const float* lB     = (const float*)d_in[4];
    const int* in_idx   = (const int*)d_in[5];
    const int* out_idx  = (const int*)d_in[6];
    float* out          = (float*)d_out;

    static bool attr_set = false;
    if (!attr_set) {
        cudaFuncSetAttribute(gemm_mma_kernel,
                             cudaFuncAttributeMaxDynamicSharedMemorySize, GEMM_SMEM);
        attr_set = true;
    }

    fold_kernel<<<dim3(ACTIVE / 256, ACTIVE), 256>>>(W, lA, lB);
    gather_kernel<<<dim3(ACTIVE / 256, M_TOK), 256>>>(x, in_idx);
    {
        int n4 = out_size / 4;
        zero_kernel<<<(n4 + 255) / 256, 256>>>((float4*)d_out, n4);
    }
    gemm_mma_kernel<<<dim3(ACTIVE / BN, M_TOK / BM), 256, GEMM_SMEM>>>(bias, out_idx, out);
    (void)n_in; (void)in_sizes;
}